// round 11
// baseline (speedup 1.0000x reference)
#include <cuda_runtime.h>
#include <cuda_fp16.h>
#include <cstdint>

#define NMAX 50000
#define EMAX 800000
#define DDIM 128

// ---------------- static scratch (no allocation allowed) -------------------
__device__ float g_Wc[DDIM * DDIM];
__device__ float g_bc[DDIM];
__device__ int   g_degi[NMAX];       // zero-invariant: gemm re-zeroes after use
__device__ int   g_off[NMAX];
__device__ int   g_cur[NMAX];
__device__ int   g_bucket[EMAX];
__device__ __align__(16) short g_xq[(size_t)NMAX * DDIM];   // x*2048 int16
// B = [W1 ; Wc]^T as fp16, layout [N=128][K=256] k-contiguous
__device__ __align__(16) __half g_Bf[128 * 256];

#define XQ_SCALE 2048.0f
#define XQ_INV   (1.0f / 2048.0f)

// ---------------- K1: hist | wcbc | x-quantize (grid-section fusion) --------
__global__ __launch_bounds__(256) void k1_kernel(
    const int* __restrict__ ecol, int E, int eb,
    const float* __restrict__ aggW, const float* __restrict__ aggb,
    const float* __restrict__ W,    const float* __restrict__ b,
    const float* __restrict__ x, int nquad)
{
    int bid = blockIdx.x;
    if (bid < eb) {
        int e = bid * 256 + threadIdx.x;
        if (e < E) atomicAdd(g_degi + ecol[e], 1);
    } else if (bid < eb + 64) {
        int k = (bid - eb) * 2 + (threadIdx.x >> 7);
        int n = threadIdx.x & 127;
        float acc = 0.f;
        #pragma unroll 8
        for (int j = 0; j < DDIM; j++)
            acc = fmaf(aggW[k * DDIM + j], W[(size_t)(DDIM + j) * DDIM + n], acc);
        g_Wc[k * DDIM + n] = acc;
        if (bid == eb && threadIdx.x < 128) {
            float bcv = b[n];
            #pragma unroll 8
            for (int j = 0; j < DDIM; j++)
                bcv = fmaf(aggb[j], W[(size_t)(DDIM + j) * DDIM + n], bcv);
            g_bc[n] = bcv;
        }
    } else {
        int q = (bid - eb - 64) * 256 + threadIdx.x;
        if (q < nquad) {
            size_t base = (size_t)q * 8;
            float4 v0 = *reinterpret_cast<const float4*>(x + base);
            float4 v1 = *reinterpret_cast<const float4*>(x + base + 4);
            short o[8];
            o[0] = (short)max(-32767, min(32767, __float2int_rn(v0.x * XQ_SCALE)));
            o[1] = (short)max(-32767, min(32767, __float2int_rn(v0.y * XQ_SCALE)));
            o[2] = (short)max(-32767, min(32767, __float2int_rn(v0.z * XQ_SCALE)));
            o[3] = (short)max(-32767, min(32767, __float2int_rn(v0.w * XQ_SCALE)));
            o[4] = (short)max(-32767, min(32767, __float2int_rn(v1.x * XQ_SCALE)));
            o[5] = (short)max(-32767, min(32767, __float2int_rn(v1.y * XQ_SCALE)));
            o[6] = (short)max(-32767, min(32767, __float2int_rn(v1.z * XQ_SCALE)));
            o[7] = (short)max(-32767, min(32767, __float2int_rn(v1.w * XQ_SCALE)));
            *reinterpret_cast<uint4*>(g_xq + base) = *reinterpret_cast<uint4*>(o);
        }
    }
}

// ---------------- scan (single block, serial chunks + shfl) -----------------
__global__ __launch_bounds__(1024) void scan_kernel(int n)
{
    __shared__ int wsum[32];
    const int tid = threadIdx.x, lane = tid & 31, wid = tid >> 5;
    const int per = (n + 1023) / 1024;
    const int s0 = min(tid * per, n);
    const int s1 = min(s0 + per, n);
    int sum = 0;
    for (int i = s0; i < s1; i++) sum += g_degi[i];
    int v = sum;
    #pragma unroll
    for (int o = 1; o < 32; o <<= 1) {
        int t = __shfl_up_sync(0xFFFFFFFFu, v, o);
        if (lane >= o) v += t;
    }
    if (lane == 31) wsum[wid] = v;
    __syncthreads();
    if (wid == 0) {
        int w = wsum[lane];
        #pragma unroll
        for (int o = 1; o < 32; o <<= 1) {
            int t = __shfl_up_sync(0xFFFFFFFFu, w, o);
            if (lane >= o) w += t;
        }
        wsum[lane] = w;
    }
    __syncthreads();
    int run = v - sum + (wid ? wsum[wid - 1] : 0);
    for (int i = s0; i < s1; i++) {
        int d = g_degi[i];
        g_off[i] = run;
        g_cur[i] = run;
        run += d;
    }
}

// ---------------- K2: binfill | B transpose + fp16 convert ------------------
__global__ __launch_bounds__(256) void k2_kernel(
    const int* __restrict__ erow, const int* __restrict__ ecol, int E, int eb,
    const float* __restrict__ W)
{
    int bid = blockIdx.x;
    if (bid < eb) {
        int e = bid * 256 + threadIdx.x;
        if (e >= E) return;
        int p = atomicAdd(g_cur + ecol[e], 1);
        g_bucket[p] = erow[e];
    } else {
        int idx = (bid - eb) * 256 + threadIdx.x;
        if (idx >= 128 * 256) return;
        int n = idx >> 8, k = idx & 255;
        float v = (k < DDIM) ? W[(size_t)k * DDIM + n]
                             : g_Wc[(size_t)(k - DDIM) * DDIM + n];
        g_Bf[idx] = __float2half_rn(v);
    }
}

// ---------------- fused gather + GEMM + ReLU + LayerNorm --------------------
// out = LN(relu(x @ W1 + agg @ Wc + bc)) * gamma + beta
// Single fp16 A image; B fp16 resident (K=256). CTA tile 64x128, 256 thr,
// warp grid 2(m) x 4(n), 2 CTAs/SM. Each warp gathers its own 8 rows' agg
// (int16 CSR accumulate) directly into the A image between the two K-halves.
#define A_STRIDE_B 272          // 128 fp16 + 16B pad
#define B_STRIDE_B 528          // 256 fp16 + 16B pad
#define TILE_M    64
#define SM_BIAS   0
#define SM_GAMMA  512
#define SM_BETA   1024
#define SM_A      1536
#define SM_BF     (SM_A + TILE_M * A_STRIDE_B)      // 18944
#define SM_TOTAL  (SM_BF + 128 * B_STRIDE_B)        // 86528 B -> 2 CTAs/SM
#define SM_STAGE  SM_A                               // 64*132*4=33792B, overlaps A+BF

__device__ __forceinline__ uint32_t smem_u32(const void* p) {
    uint32_t a;
    asm("{ .reg .u64 t; cvta.to.shared.u64 t, %1; cvt.u32.u64 %0, t; }"
        : "=r"(a) : "l"(p));
    return a;
}
__device__ __forceinline__ void ldmx4(uint32_t* r, uint32_t addr) {
    asm volatile("ldmatrix.sync.aligned.m8n8.x4.shared.b16 {%0,%1,%2,%3}, [%4];"
                 : "=r"(r[0]), "=r"(r[1]), "=r"(r[2]), "=r"(r[3]) : "r"(addr));
}
__device__ __forceinline__ void mma_f16(float* c, const uint32_t* a, uint32_t b0, uint32_t b1) {
    asm volatile(
        "mma.sync.aligned.m16n8k16.row.col.f32.f16.f16.f32 "
        "{%0,%1,%2,%3}, {%4,%5,%6,%7}, {%8,%9}, {%0,%1,%2,%3};"
        : "+f"(c[0]), "+f"(c[1]), "+f"(c[2]), "+f"(c[3])
        : "r"(a[0]), "r"(a[1]), "r"(a[2]), "r"(a[3]), "r"(b0), "r"(b1));
}

__global__ __launch_bounds__(256, 2) void mma_gemm_kernel(
    const float* __restrict__ x,
    const float* __restrict__ gamma,
    const float* __restrict__ beta,
    float* __restrict__ out,
    int M)
{
    extern __shared__ char smem[];
    const uint32_t sb = smem_u32(smem);
    const int tid  = threadIdx.x;
    const int wid  = tid >> 5;
    const int lane = tid & 31;
    const int base_row = blockIdx.x * TILE_M;
    const int warp_m = wid & 1;
    const int warp_n = wid >> 1;

    if (tid < 32) {
        reinterpret_cast<float4*>(smem + SM_BIAS)[tid]  =
            reinterpret_cast<const float4*>(g_bc)[tid];
        reinterpret_cast<float4*>(smem + SM_GAMMA)[tid] =
            reinterpret_cast<const float4*>(gamma)[tid];
        reinterpret_cast<float4*>(smem + SM_BETA)[tid]  =
            reinterpret_cast<const float4*>(beta)[tid];
    }
    // B fp16 -> smem: 128 rows x 512B
    #pragma unroll
    for (int i = 0; i < 16; i++) {
        int idx = tid + i * 256;            // 0..4095 uint4
        int n = idx >> 5, q = idx & 31;
        *reinterpret_cast<uint4*>(smem + SM_BF + n * B_STRIDE_B + q * 16) =
            *reinterpret_cast<const uint4*>(g_Bf + n * 256 + q * 8);
    }

    // fill x half: 64 rows x 32 float4 -> fp16 A image
    #pragma unroll
    for (int i = 0; i < 8; i++) {
        int idx = tid + i * 256;
        int row = idx >> 5;
        int kq  = (idx & 31) * 4;
        int grow = base_row + row;
        if (grow >= M) grow = M - 1;
        float4 v = *reinterpret_cast<const float4*>(x + (size_t)grow * DDIM + kq);
        __half h0 = __float2half_rn(v.x);
        __half h1 = __float2half_rn(v.y);
        __half h2 = __float2half_rn(v.z);
        __half h3 = __float2half_rn(v.w);
        uint2 hw;
        hw.x = ((uint32_t)__half_as_ushort(h1) << 16) | __half_as_ushort(h0);
        hw.y = ((uint32_t)__half_as_ushort(h3) << 16) | __half_as_ushort(h2);
        *reinterpret_cast<uint2*>(smem + SM_A + (uint32_t)row * A_STRIDE_B + (uint32_t)kq * 2) = hw;
    }
    __syncthreads();

    float acc[2][4][4];
    #pragma unroll
    for (int i = 0; i < 2; i++)
        #pragma unroll
        for (int j = 0; j < 4; j++)
            #pragma unroll
            for (int c = 0; c < 4; c++) acc[i][j][c] = 0.f;

    const int a_row_lo = (lane & 7) + ((lane >> 3) & 1) * 8;
    const int a_koff   = ((lane >> 4) & 1) * 8;
    const int b_nrow   = warp_n * 32 + (lane & 7) + ((lane >> 4) & 1) * 8;
    const int b_koff   = ((lane >> 3) & 1) * 8;

    auto compute_half = [&](int h) {
        #pragma unroll
        for (int kc = 0; kc < 8; kc++) {
            const int kA = kc * 16 + a_koff;
            const int kB = h * 128 + kc * 16 + b_koff;
            uint32_t ah[2][4];
            #pragma unroll
            for (int i = 0; i < 2; i++) {
                int row = warp_m * 32 + i * 16 + a_row_lo;
                ldmx4(ah[i], sb + SM_A + (uint32_t)row * A_STRIDE_B + (uint32_t)kA * 2);
            }
            uint32_t bf[2][4];
            #pragma unroll
            for (int p = 0; p < 2; p++) {
                uint32_t off = (uint32_t)(b_nrow + p * 16) * B_STRIDE_B + (uint32_t)kB * 2;
                ldmx4(bf[p], sb + SM_BF + off);
            }
            #pragma unroll
            for (int i = 0; i < 2; i++)
                #pragma unroll
                for (int p = 0; p < 2; p++) {
                    mma_f16(acc[i][2 * p],     ah[i], bf[p][0], bf[p][1]);
                    mma_f16(acc[i][2 * p + 1], ah[i], bf[p][2], bf[p][3]);
                }
        }
    };

    compute_half(0);
    __syncthreads();            // all warps done reading x image

    // ---- fused gather: warp wid owns rows wid*8 .. wid*8+7 ----
    #pragma unroll 1
    for (int nr = 0; nr < 8; nr++) {
        int row  = wid * 8 + nr;
        int grow = base_row + row;
        int a0 = 0, a1 = 0, a2 = 0, a3 = 0;
        float rd = 0.f;
        if (grow < M) {
            int s = g_off[grow];
            int d = g_degi[grow];
            int j = 0;
            for (; j + 4 <= d; j += 4) {
                int r0 = g_bucket[s + j + 0];
                int r1 = g_bucket[s + j + 1];
                int r2 = g_bucket[s + j + 2];
                int r3 = g_bucket[s + j + 3];
                uint2 w0 = *reinterpret_cast<const uint2*>(g_xq + (size_t)r0 * DDIM + lane * 4);
                uint2 w1 = *reinterpret_cast<const uint2*>(g_xq + (size_t)r1 * DDIM + lane * 4);
                uint2 w2 = *reinterpret_cast<const uint2*>(g_xq + (size_t)r2 * DDIM + lane * 4);
                uint2 w3 = *reinterpret_cast<const uint2*>(g_xq + (size_t)r3 * DDIM + lane * 4);
                a0 += (int)(short)(w0.x) + (int)(short)(w1.x) + (int)(short)(w2.x) + (int)(short)(w3.x);
                a1 += ((int)w0.x >> 16) + ((int)w1.x >> 16) + ((int)w2.x >> 16) + ((int)w3.x >> 16);
                a2 += (int)(short)(w0.y) + (int)(short)(w1.y) + (int)(short)(w2.y) + (int)(short)(w3.y);
                a3 += ((int)w0.y >> 16) + ((int)w1.y >> 16) + ((int)w2.y >> 16) + ((int)w3.y >> 16);
            }
            for (; j < d; j++) {
                int r = g_bucket[s + j];
                uint2 w0 = *reinterpret_cast<const uint2*>(g_xq + (size_t)r * DDIM + lane * 4);
                a0 += (int)(short)(w0.x);
                a1 += ((int)w0.x >> 16);
                a2 += (int)(short)(w0.y);
                a3 += ((int)w0.y >> 16);
            }
            rd = XQ_INV / fmaxf((float)d, 1.0f);
            if (lane == 0) g_degi[grow] = 0;   // restore zero-invariant (canonical row only)
        }
        __half h0 = __float2half_rn((float)a0 * rd);
        __half h1 = __float2half_rn((float)a1 * rd);
        __half h2 = __float2half_rn((float)a2 * rd);
        __half h3 = __float2half_rn((float)a3 * rd);
        uint2 hw;
        hw.x = ((uint32_t)__half_as_ushort(h1) << 16) | __half_as_ushort(h0);
        hw.y = ((uint32_t)__half_as_ushort(h3) << 16) | __half_as_ushort(h2);
        *reinterpret_cast<uint2*>(smem + SM_A + (uint32_t)row * A_STRIDE_B + (uint32_t)lane * 8) = hw;
    }
    __syncthreads();
    compute_half(1);
    __syncthreads();

    // stage accumulators [64][132] (reuses A+B region)
    float* stg = reinterpret_cast<float*>(smem + SM_STAGE);
    #pragma unroll
    for (int i = 0; i < 2; i++) {
        int row0 = warp_m * 32 + i * 16 + (lane >> 2);
        #pragma unroll
        for (int j = 0; j < 4; j++) {
            int col = warp_n * 32 + j * 8 + (lane & 3) * 2;
            *reinterpret_cast<float2*>(stg + row0 * 132 + col) =
                make_float2(acc[i][j][0], acc[i][j][1]);
            *reinterpret_cast<float2*>(stg + (row0 + 8) * 132 + col) =
                make_float2(acc[i][j][2], acc[i][j][3]);
        }
    }
    __syncthreads();

    // bias + ReLU + LN; warp wid -> rows wid*8..+7, lane owns 4 cols
    float4 b4 = *reinterpret_cast<const float4*>(smem + SM_BIAS  + lane * 16);
    float4 g4 = *reinterpret_cast<const float4*>(smem + SM_GAMMA + lane * 16);
    float4 t4 = *reinterpret_cast<const float4*>(smem + SM_BETA  + lane * 16);
    #pragma unroll
    for (int ii = 0; ii < 8; ii++) {
        int r = wid * 8 + ii;
        int grow = base_row + r;
        if (grow >= M) continue;
        float4 v = *reinterpret_cast<const float4*>(stg + r * 132 + lane * 4);
        v.x = fmaxf(v.x + b4.x, 0.f);
        v.y = fmaxf(v.y + b4.y, 0.f);
        v.z = fmaxf(v.z + b4.z, 0.f);
        v.w = fmaxf(v.w + b4.w, 0.f);
        float s  = v.x + v.y + v.z + v.w;
        float sq = v.x * v.x + v.y * v.y + v.z * v.z + v.w * v.w;
        #pragma unroll
        for (int o = 16; o > 0; o >>= 1) {
            s  += __shfl_xor_sync(0xFFFFFFFFu, s, o);
            sq += __shfl_xor_sync(0xFFFFFFFFu, sq, o);
        }
        float mean = s * (1.0f / DDIM);
        float var  = sq * (1.0f / DDIM) - mean * mean;
        float rstd = rsqrtf(var + 1e-5f);
        float4 o;
        o.x = (v.x - mean) * rstd * g4.x + t4.x;
        o.y = (v.y - mean) * rstd * g4.y + t4.y;
        o.z = (v.z - mean) * rstd * g4.z + t4.z;
        o.w = (v.w - mean) * rstd * g4.w + t4.w;
        *reinterpret_cast<float4*>(out + (size_t)grow * DDIM + lane * 4) = o;
    }
}

// ---------------------------------------------------------------------------
extern "C" void kernel_launch(void* const* d_in, const int* in_sizes, int n_in,
                              void* d_out, int out_size)
{
    const float* x     = (const float*)d_in[0];
    const int*   ei    = (const int*)d_in[1];
    const float* aggW  = (const float*)d_in[2];
    const float* aggb  = (const float*)d_in[3];
    const float* W     = (const float*)d_in[4];
    const float* b     = (const float*)d_in[5];
    const float* gamma = (const float*)d_in[6];
    const float* beta  = (const float*)d_in[7];
    float* out = (float*)d_out;

    const int E = in_sizes[1] / 2;
    const int M = in_sizes[0] / DDIM;

    cudaFuncSetAttribute(mma_gemm_kernel,
                         cudaFuncAttributeMaxDynamicSharedMemorySize, SM_TOTAL);

    const int* erow = ei;
    const int* ecol = ei + E;
    const int eb = (E + 255) / 256;
    const int nquad = (M * DDIM) / 8;
    const int pb = (nquad + 255) / 256;
    const int bb = (128 * 256 + 255) / 256;

    k1_kernel<<<eb + 64 + pb, 256>>>(ecol, E, eb, aggW, aggb, W, b, x, nquad);
    scan_kernel<<<1, 1024>>>(M);
    k2_kernel<<<eb + bb, 256>>>(erow, ecol, E, eb, W);
    mma_gemm_kernel<<<(M + TILE_M - 1) / TILE_M, 256, SM_TOTAL>>>(x, gamma, beta, out, M);
}

// round 12
// speedup vs baseline: 2.0394x; 2.0394x over previous
#include <cuda_runtime.h>
#include <cuda_fp16.h>
#include <cstdint>

#define NMAX 50000
#define EMAX 800000
#define DDIM 128

// ---------------- static scratch (no allocation allowed) -------------------
__device__ float g_agg[(size_t)NMAX * DDIM];
__device__ float g_Wc[DDIM * DDIM];
__device__ float g_bc[DDIM];
__device__ int   g_degi[NMAX];       // zero-invariant: gather re-zeroes after use
__device__ int   g_off[NMAX];
__device__ int   g_cur[NMAX];
__device__ int   g_bucket[EMAX];
__device__ int   g_bsum[64];         // per-block scan sums
__device__ __align__(16) short g_xq[(size_t)NMAX * DDIM];   // x*2048 int16
__device__ __align__(16) __half g_Bf[128 * 256];            // [W1;Wc]^T fp16 [N][K]

#define XQ_SCALE 2048.0f
#define XQ_INV   (1.0f / 2048.0f)

// ---------------- K1: hist | wcbc | x-quantize (grid-section fusion) --------
__global__ __launch_bounds__(256) void k1_kernel(
    const int* __restrict__ ecol, int E, int eb,
    const float* __restrict__ aggW, const float* __restrict__ aggb,
    const float* __restrict__ W,    const float* __restrict__ b,
    const float* __restrict__ x, int nquad)
{
    int bid = blockIdx.x;
    if (bid < eb) {
        int e = bid * 256 + threadIdx.x;
        if (e < E) atomicAdd(g_degi + ecol[e], 1);
    } else if (bid < eb + 64) {
        int k = (bid - eb) * 2 + (threadIdx.x >> 7);
        int n = threadIdx.x & 127;
        float acc = 0.f;
        #pragma unroll 8
        for (int j = 0; j < DDIM; j++)
            acc = fmaf(aggW[k * DDIM + j], W[(size_t)(DDIM + j) * DDIM + n], acc);
        g_Wc[k * DDIM + n] = acc;
        if (bid == eb && threadIdx.x < 128) {
            float bcv = b[n];
            #pragma unroll 8
            for (int j = 0; j < DDIM; j++)
                bcv = fmaf(aggb[j], W[(size_t)(DDIM + j) * DDIM + n], bcv);
            g_bc[n] = bcv;
        }
    } else {
        int q = (bid - eb - 64) * 256 + threadIdx.x;
        if (q < nquad) {
            size_t base = (size_t)q * 8;
            float4 v0 = *reinterpret_cast<const float4*>(x + base);
            float4 v1 = *reinterpret_cast<const float4*>(x + base + 4);
            short o[8];
            o[0] = (short)max(-32767, min(32767, __float2int_rn(v0.x * XQ_SCALE)));
            o[1] = (short)max(-32767, min(32767, __float2int_rn(v0.y * XQ_SCALE)));
            o[2] = (short)max(-32767, min(32767, __float2int_rn(v0.z * XQ_SCALE)));
            o[3] = (short)max(-32767, min(32767, __float2int_rn(v0.w * XQ_SCALE)));
            o[4] = (short)max(-32767, min(32767, __float2int_rn(v1.x * XQ_SCALE)));
            o[5] = (short)max(-32767, min(32767, __float2int_rn(v1.y * XQ_SCALE)));
            o[6] = (short)max(-32767, min(32767, __float2int_rn(v1.z * XQ_SCALE)));
            o[7] = (short)max(-32767, min(32767, __float2int_rn(v1.w * XQ_SCALE)));
            *reinterpret_cast<uint4*>(g_xq + base) = *reinterpret_cast<uint4*>(o);
        }
    }
}

// ---------------- scan1: per-block exclusive scan + block sums --------------
__global__ __launch_bounds__(1024) void scan1_kernel(int n)
{
    __shared__ int wsum[32];
    const int tid = threadIdx.x, lane = tid & 31, wid = tid >> 5;
    const int i = blockIdx.x * 1024 + tid;
    int v = (i < n) ? g_degi[i] : 0;
    int inc = v;
    #pragma unroll
    for (int o = 1; o < 32; o <<= 1) {
        int t = __shfl_up_sync(0xFFFFFFFFu, inc, o);
        if (lane >= o) inc += t;
    }
    if (lane == 31) wsum[wid] = inc;
    __syncthreads();
    if (wid == 0) {
        int w = wsum[lane];
        #pragma unroll
        for (int o = 1; o < 32; o <<= 1) {
            int t = __shfl_up_sync(0xFFFFFFFFu, w, o);
            if (lane >= o) w += t;
        }
        wsum[lane] = w;
    }
    __syncthreads();
    int excl = inc - v + (wid ? wsum[wid - 1] : 0);
    if (i < n) g_off[i] = excl;
    if (tid == 1023) g_bsum[blockIdx.x] = excl + v;
}

// ---------------- scan2: add block prefix, write g_off/g_cur ----------------
__global__ __launch_bounds__(1024) void scan2_kernel(int n)
{
    __shared__ int off_s;
    const int tid = threadIdx.x, lane = tid & 31;
    const int bid = blockIdx.x;
    if (tid < 32) {
        int o = 0;
        if (lane < bid) o = g_bsum[lane];
        if (lane + 32 < bid) o += g_bsum[lane + 32];
        #pragma unroll
        for (int s = 16; s > 0; s >>= 1)
            o += __shfl_xor_sync(0xFFFFFFFFu, o, s);
        if (lane == 0) off_s = o;
    }
    __syncthreads();
    int i = bid * 1024 + tid;
    if (i < n) {
        int v = g_off[i] + off_s;
        g_off[i] = v;
        g_cur[i] = v;
    }
}

// ---------------- K2: binfill | B transpose + fp16 convert ------------------
__global__ __launch_bounds__(256) void k2_kernel(
    const int* __restrict__ erow, const int* __restrict__ ecol, int E, int eb,
    const float* __restrict__ W)
{
    int bid = blockIdx.x;
    if (bid < eb) {
        int e = bid * 256 + threadIdx.x;
        if (e >= E) return;
        int p = atomicAdd(g_cur + ecol[e], 1);
        g_bucket[p] = erow[e];
    } else {
        int idx = (bid - eb) * 256 + threadIdx.x;
        if (idx >= 128 * 256) return;
        int n = idx >> 8, k = idx & 255;
        float v = (k < DDIM) ? W[(size_t)k * DDIM + n]
                             : g_Wc[(size_t)(k - DDIM) * DDIM + n];
        g_Bf[idx] = __float2half_rn(v);
    }
}

// ---------------- gather-mean from int16 + g_degi self-clear ----------------
__global__ __launch_bounds__(256) void gather_kernel(int M)
{
    int w    = (blockIdx.x * blockDim.x + threadIdx.x) >> 5;
    int lane = threadIdx.x & 31;
    if (w >= M) return;
    int s = g_off[w];
    int d = g_degi[w];
    int a0 = 0, a1 = 0, a2 = 0, a3 = 0;
    int j = 0;
    for (; j + 4 <= d; j += 4) {
        int r0 = g_bucket[s + j + 0];
        int r1 = g_bucket[s + j + 1];
        int r2 = g_bucket[s + j + 2];
        int r3 = g_bucket[s + j + 3];
        uint2 w0 = *reinterpret_cast<const uint2*>(g_xq + (size_t)r0 * DDIM + lane * 4);
        uint2 w1 = *reinterpret_cast<const uint2*>(g_xq + (size_t)r1 * DDIM + lane * 4);
        uint2 w2 = *reinterpret_cast<const uint2*>(g_xq + (size_t)r2 * DDIM + lane * 4);
        uint2 w3 = *reinterpret_cast<const uint2*>(g_xq + (size_t)r3 * DDIM + lane * 4);
        a0 += (int)(short)(w0.x) + (int)(short)(w1.x) + (int)(short)(w2.x) + (int)(short)(w3.x);
        a1 += ((int)w0.x >> 16) + ((int)w1.x >> 16) + ((int)w2.x >> 16) + ((int)w3.x >> 16);
        a2 += (int)(short)(w0.y) + (int)(short)(w1.y) + (int)(short)(w2.y) + (int)(short)(w3.y);
        a3 += ((int)w0.y >> 16) + ((int)w1.y >> 16) + ((int)w2.y >> 16) + ((int)w3.y >> 16);
    }
    for (; j < d; j++) {
        int r = g_bucket[s + j];
        uint2 w0 = *reinterpret_cast<const uint2*>(g_xq + (size_t)r * DDIM + lane * 4);
        a0 += (int)(short)(w0.x);
        a1 += ((int)w0.x >> 16);
        a2 += (int)(short)(w0.y);
        a3 += ((int)w0.y >> 16);
    }
    float rd = XQ_INV / fmaxf((float)d, 1.0f);
    float4 o = make_float4((float)a0 * rd, (float)a1 * rd,
                           (float)a2 * rd, (float)a3 * rd);
    *reinterpret_cast<float4*>(g_agg + (size_t)w * DDIM + lane * 4) = o;
    if (lane == 0) g_degi[w] = 0;      // restore zero-invariant for next call
}

// ---------------- GEMM + ReLU + LayerNorm (single-pass fp16) ----------------
// CTA tile 64x128, 256 threads, warp grid 2(m) x 4(n), 2 CTAs/SM.
#define A_STRIDE_B 272
#define B_STRIDE_B 528
#define TILE_M    64
#define SM_BIAS   0
#define SM_GAMMA  512
#define SM_BETA   1024
#define SM_A      1536
#define SM_BF     (SM_A + TILE_M * A_STRIDE_B)      // 18944
#define SM_TOTAL  (SM_BF + 128 * B_STRIDE_B)        // 86528 B -> 2 CTAs/SM
#define SM_STAGE  SM_A                               // 64*132*4=33792B overlaps A+BF

__device__ __forceinline__ uint32_t smem_u32(const void* p) {
    uint32_t a;
    asm("{ .reg .u64 t; cvta.to.shared.u64 t, %1; cvt.u32.u64 %0, t; }"
        : "=r"(a) : "l"(p));
    return a;
}
__device__ __forceinline__ void ldmx4(uint32_t* r, uint32_t addr) {
    asm volatile("ldmatrix.sync.aligned.m8n8.x4.shared.b16 {%0,%1,%2,%3}, [%4];"
                 : "=r"(r[0]), "=r"(r[1]), "=r"(r[2]), "=r"(r[3]) : "r"(addr));
}
__device__ __forceinline__ void mma_f16(float* c, const uint32_t* a, uint32_t b0, uint32_t b1) {
    asm volatile(
        "mma.sync.aligned.m16n8k16.row.col.f32.f16.f16.f32 "
        "{%0,%1,%2,%3}, {%4,%5,%6,%7}, {%8,%9}, {%0,%1,%2,%3};"
        : "+f"(c[0]), "+f"(c[1]), "+f"(c[2]), "+f"(c[3])
        : "r"(a[0]), "r"(a[1]), "r"(a[2]), "r"(a[3]), "r"(b0), "r"(b1));
}

__global__ __launch_bounds__(256, 2) void mma_gemm_kernel(
    const float* __restrict__ x,
    const float* __restrict__ gamma,
    const float* __restrict__ beta,
    float* __restrict__ out,
    int M)
{
    extern __shared__ char smem[];
    const uint32_t sb = smem_u32(smem);
    const int tid  = threadIdx.x;
    const int wid  = tid >> 5;
    const int lane = tid & 31;
    const int base_row = blockIdx.x * TILE_M;
    const int warp_m = wid & 1;
    const int warp_n = wid >> 1;

    if (tid < 32) {
        reinterpret_cast<float4*>(smem + SM_BIAS)[tid]  =
            reinterpret_cast<const float4*>(g_bc)[tid];
        reinterpret_cast<float4*>(smem + SM_GAMMA)[tid] =
            reinterpret_cast<const float4*>(gamma)[tid];
        reinterpret_cast<float4*>(smem + SM_BETA)[tid]  =
            reinterpret_cast<const float4*>(beta)[tid];
    }
    // B fp16 -> smem: 128 rows x 512B
    #pragma unroll
    for (int i = 0; i < 16; i++) {
        int idx = tid + i * 256;
        int n = idx >> 5, q = idx & 31;
        *reinterpret_cast<uint4*>(smem + SM_BF + n * B_STRIDE_B + q * 16) =
            *reinterpret_cast<const uint4*>(g_Bf + n * 256 + q * 8);
    }

    auto cvt_store = [&](float4 v, int row, int kq) {
        __half h0 = __float2half_rn(v.x);
        __half h1 = __float2half_rn(v.y);
        __half h2 = __float2half_rn(v.z);
        __half h3 = __float2half_rn(v.w);
        uint2 hw;
        hw.x = ((uint32_t)__half_as_ushort(h1) << 16) | __half_as_ushort(h0);
        hw.y = ((uint32_t)__half_as_ushort(h3) << 16) | __half_as_ushort(h2);
        *reinterpret_cast<uint2*>(smem + SM_A + (uint32_t)row * A_STRIDE_B + (uint32_t)kq * 2) = hw;
    };

    // fill x half: 64 rows x 32 float4
    #pragma unroll
    for (int i = 0; i < 8; i++) {
        int idx = tid + i * 256;
        int row = idx >> 5;
        int kq  = (idx & 31) * 4;
        int grow = base_row + row;
        if (grow >= M) grow = M - 1;
        cvt_store(*reinterpret_cast<const float4*>(x + (size_t)grow * DDIM + kq), row, kq);
    }
    __syncthreads();

    // prefetch agg half into registers
    float4 pre[8];
    #pragma unroll
    for (int i = 0; i < 8; i++) {
        int idx = tid + i * 256;
        int row = idx >> 5;
        int kq  = (idx & 31) * 4;
        int grow = base_row + row;
        if (grow >= M) grow = M - 1;
        pre[i] = *reinterpret_cast<const float4*>(g_agg + (size_t)grow * DDIM + kq);
    }

    float acc[2][4][4];
    #pragma unroll
    for (int i = 0; i < 2; i++)
        #pragma unroll
        for (int j = 0; j < 4; j++)
            #pragma unroll
            for (int c = 0; c < 4; c++) acc[i][j][c] = 0.f;

    const int a_row_lo = (lane & 7) + ((lane >> 3) & 1) * 8;
    const int a_koff   = ((lane >> 4) & 1) * 8;
    const int b_nrow   = warp_n * 32 + (lane & 7) + ((lane >> 4) & 1) * 8;
    const int b_koff   = ((lane >> 3) & 1) * 8;

    auto compute_half = [&](int h) {
        #pragma unroll
        for (int kc = 0; kc < 8; kc++) {
            const int kA = kc * 16 + a_koff;
            const int kB = h * 128 + kc * 16 + b_koff;
            uint32_t ah[2][4];
            #pragma unroll
            for (int i = 0; i < 2; i++) {
                int row = warp_m * 32 + i * 16 + a_row_lo;
                ldmx4(ah[i], sb + SM_A + (uint32_t)row * A_STRIDE_B + (uint32_t)kA * 2);
            }
            uint32_t bf[2][4];
            #pragma unroll
            for (int p = 0; p < 2; p++) {
                uint32_t off = (uint32_t)(b_nrow + p * 16) * B_STRIDE_B + (uint32_t)kB * 2;
                ldmx4(bf[p], sb + SM_BF + off);
            }
            #pragma unroll
            for (int i = 0; i < 2; i++)
                #pragma unroll
                for (int p = 0; p < 2; p++) {
                    mma_f16(acc[i][2 * p],     ah[i], bf[p][0], bf[p][1]);
                    mma_f16(acc[i][2 * p + 1], ah[i], bf[p][2], bf[p][3]);
                }
        }
    };

    compute_half(0);
    __syncthreads();            // done reading x image

    // store prefetched agg half
    #pragma unroll
    for (int i = 0; i < 8; i++) {
        int idx = tid + i * 256;
        int row = idx >> 5;
        int kq  = (idx & 31) * 4;
        cvt_store(pre[i], row, kq);
    }
    __syncthreads();
    compute_half(1);
    __syncthreads();

    // stage accumulators [64][132]
    float* stg = reinterpret_cast<float*>(smem + SM_STAGE);
    #pragma unroll
    for (int i = 0; i < 2; i++) {
        int row0 = warp_m * 32 + i * 16 + (lane >> 2);
        #pragma unroll
        for (int j = 0; j < 4; j++) {
            int col = warp_n * 32 + j * 8 + (lane & 3) * 2;
            *reinterpret_cast<float2*>(stg + row0 * 132 + col) =
                make_float2(acc[i][j][0], acc[i][j][1]);
            *reinterpret_cast<float2*>(stg + (row0 + 8) * 132 + col) =
                make_float2(acc[i][j][2], acc[i][j][3]);
        }
    }
    __syncthreads();

    float4 b4 = *reinterpret_cast<const float4*>(smem + SM_BIAS  + lane * 16);
    float4 g4 = *reinterpret_cast<const float4*>(smem + SM_GAMMA + lane * 16);
    float4 t4 = *reinterpret_cast<const float4*>(smem + SM_BETA  + lane * 16);
    #pragma unroll
    for (int ii = 0; ii < 8; ii++) {
        int r = wid * 8 + ii;
        int grow = base_row + r;
        if (grow >= M) continue;
        float4 v = *reinterpret_cast<const float4*>(stg + r * 132 + lane * 4);
        v.x = fmaxf(v.x + b4.x, 0.f);
        v.y = fmaxf(v.y + b4.y, 0.f);
        v.z = fmaxf(v.z + b4.z, 0.f);
        v.w = fmaxf(v.w + b4.w, 0.f);
        float s  = v.x + v.y + v.z + v.w;
        float sq = v.x * v.x + v.y * v.y + v.z * v.z + v.w * v.w;
        #pragma unroll
        for (int o = 16; o > 0; o >>= 1) {
            s  += __shfl_xor_sync(0xFFFFFFFFu, s, o);
            sq += __shfl_xor_sync(0xFFFFFFFFu, sq, o);
        }
        float mean = s * (1.0f / DDIM);
        float var  = sq * (1.0f / DDIM) - mean * mean;
        float rstd = rsqrtf(var + 1e-5f);
        float4 o;
        o.x = (v.x - mean) * rstd * g4.x + t4.x;
        o.y = (v.y - mean) * rstd * g4.y + t4.y;
        o.z = (v.z - mean) * rstd * g4.z + t4.z;
        o.w = (v.w - mean) * rstd * g4.w + t4.w;
        *reinterpret_cast<float4*>(out + (size_t)grow * DDIM + lane * 4) = o;
    }
}

// ---------------------------------------------------------------------------
extern "C" void kernel_launch(void* const* d_in, const int* in_sizes, int n_in,
                              void* d_out, int out_size)
{
    const float* x     = (const float*)d_in[0];
    const int*   ei    = (const int*)d_in[1];
    const float* aggW  = (const float*)d_in[2];
    const float* aggb  = (const float*)d_in[3];
    const float* W     = (const float*)d_in[4];
    const float* b     = (const float*)d_in[5];
    const float* gamma = (const float*)d_in[6];
    const float* beta  = (const float*)d_in[7];
    float* out = (float*)d_out;

    const int E = in_sizes[1] / 2;
    const int M = in_sizes[0] / DDIM;

    cudaFuncSetAttribute(mma_gemm_kernel,
                         cudaFuncAttributeMaxDynamicSharedMemorySize, SM_TOTAL);

    const int* erow = ei;
    const int* ecol = ei + E;
    const int eb = (E + 255) / 256;
    const int nquad = (M * DDIM) / 8;
    const int pb = (nquad + 255) / 256;
    const int bb = (128 * 256 + 255) / 256;
    const int sbk = (M + 1023) / 1024;

    k1_kernel<<<eb + 64 + pb, 256>>>(ecol, E, eb, aggW, aggb, W, b, x, nquad);
    scan1_kernel<<<sbk, 1024>>>(M);
    scan2_kernel<<<sbk, 1024>>>(M);
    k2_kernel<<<eb + bb, 256>>>(erow, ecol, E, eb, W);
    gather_kernel<<<(M * 32 + 255) / 256, 256>>>(M);
    mma_gemm_kernel<<<(M + TILE_M - 1) / TILE_M, 256, SM_TOTAL>>>(x, gamma, beta, out, M);
}